// round 15
// baseline (speedup 1.0000x reference)
#include <cuda_runtime.h>
#include <cuda_fp16.h>
#include <cstdint>

#define N_NODES 50000
#define N_EDGES 800000
#define F_IN    128
#define F_HID   128
#define F_OUT   64
#define SCAN_B  1024
#define SCAN_NB ((N_NODES + SCAN_B - 1) / SCAN_B)   // 49
#define GB1     ((N_NODES + 127) / 128)             // 391 gemm blocks (TM=128)
#define DEGB    ((N_EDGES + 255) / 256)             // 3125 deg blocks
#define FILLB   ((N_EDGES + 1023) / 1024)           // 782 fill blocks (4 edges/thread)

// ---- zero-init region (single memset): [0,N)=deg_out [N,2N)=deg_in ----
#define A_DEGO  0
#define A_DEGI  N_NODES
#define A_TOTAL (2 * N_NODES)
__device__ __align__(16) int    g_atomic[A_TOTAL];

__device__ __align__(16) __half g_z1h[N_NODES * F_HID];  // (h*norm_out)@W1      fp16 [N,128]
__device__ __align__(16) __half g_h1h[N_NODES * F_HID];  // relu layer1*norm_out fp16 [N,128]
__device__ __align__(16) __half g_z2h[N_NODES * F_OUT];  // h1@W2                fp16 [N,64]
__device__ __align__(16) float  g_norm_out[N_NODES];
__device__ __align__(16) float  g_norm_in [N_NODES];
__device__ __align__(16) int    g_row_start[N_NODES];
__device__ __align__(16) int    g_cursor[N_NODES];
__device__ __align__(16) int    g_bsum[64];
__device__ __align__(16) int    g_csr_src[N_EDGES];

__device__ __forceinline__ int clampi(int v) {
    return v < 0 ? 0 : (v >= N_NODES ? N_NODES - 1 : v);
}

__device__ __forceinline__ uint32_t s2u(const void* p) {
    uint32_t a;
    asm("{ .reg .u64 t; cvta.to.shared.u64 t, %1; cvt.u32.u64 %0, t; }" : "=r"(a) : "l"(p));
    return a;
}

__device__ __forceinline__ void ldsm_x4(uint32_t& r0, uint32_t& r1, uint32_t& r2, uint32_t& r3, uint32_t addr) {
    asm volatile("ldmatrix.sync.aligned.m8n8.x4.shared.b16 {%0,%1,%2,%3}, [%4];"
                 : "=r"(r0), "=r"(r1), "=r"(r2), "=r"(r3) : "r"(addr));
}

__device__ __forceinline__ void ldsm_x4t(uint32_t& r0, uint32_t& r1, uint32_t& r2, uint32_t& r3, uint32_t addr) {
    asm volatile("ldmatrix.sync.aligned.m8n8.x4.trans.shared.b16 {%0,%1,%2,%3}, [%4];"
                 : "=r"(r0), "=r"(r1), "=r"(r2), "=r"(r3) : "r"(addr));
}

__device__ __forceinline__ void mma16816(float* c, const uint32_t* a, const uint32_t* b) {
    asm volatile("mma.sync.aligned.m16n8k16.row.col.f32.f16.f16.f32 "
                 "{%0,%1,%2,%3}, {%4,%5,%6,%7}, {%8,%9}, {%0,%1,%2,%3};"
                 : "+f"(c[0]), "+f"(c[1]), "+f"(c[2]), "+f"(c[3])
                 : "r"(a[0]), "r"(a[1]), "r"(a[2]), "r"(a[3]), "r"(b[0]), "r"(b[1]));
}

__device__ __forceinline__ uint32_t hadd2(uint32_t a, uint32_t b) {
    uint32_t c;
    asm("add.f16x2 %0, %1, %2;" : "=r"(c) : "r"(a), "r"(b));
    return c;
}

__device__ __forceinline__ uint4 f8_to_h8(float4 v0, float4 v1, float s) {
    __half2 h0 = __floats2half2_rn(v0.x * s, v0.y * s);
    __half2 h1 = __floats2half2_rn(v0.z * s, v0.w * s);
    __half2 h2 = __floats2half2_rn(v1.x * s, v1.y * s);
    __half2 h3 = __floats2half2_rn(v1.z * s, v1.w * s);
    uint4 u;
    u.x = *(uint32_t*)&h0; u.y = *(uint32_t*)&h1;
    u.z = *(uint32_t*)&h2; u.w = *(uint32_t*)&h3;
    return u;
}

// ---------------- degree histogram ----------------
__global__ void k_deg(const int* __restrict__ src, const int* __restrict__ dst) {
    int e = blockIdx.x * blockDim.x + threadIdx.x;
    if (e < N_EDGES) {
        atomicAdd(&g_atomic[A_DEGO + clampi(src[e])], 1);
        atomicAdd(&g_atomic[A_DEGI + clampi(dst[e])], 1);
    }
}

// ---------------- norms (split out so GEMM1 can start right after) ----------------
__global__ void k_norm() {
    int i = blockIdx.x * blockDim.x + threadIdx.x;
    if (i < N_NODES) {
        g_norm_out[i] = rsqrtf((float)max(g_atomic[A_DEGO + i], 1));
        g_norm_in [i] = rsqrtf((float)max(g_atomic[A_DEGI + i], 1));
    }
}

// ---------------- scan1: block-local scan of deg_in ----------------
__global__ void k_scan1() {
    __shared__ int wt[32];
    int i    = blockIdx.x * SCAN_B + threadIdx.x;
    int lane = threadIdx.x & 31;
    int wid  = threadIdx.x >> 5;
    int v = (i < N_NODES) ? g_atomic[A_DEGI + i] : 0;
    int x = v;
#pragma unroll
    for (int off = 1; off < 32; off <<= 1) {
        int t = __shfl_up_sync(0xffffffffu, x, off);
        if (lane >= off) x += t;
    }
    if (lane == 31) wt[wid] = x;
    __syncthreads();
    if (wid == 0) {
        int y = wt[lane];
#pragma unroll
        for (int off = 1; off < 32; off <<= 1) {
            int t = __shfl_up_sync(0xffffffffu, y, off);
            if (lane >= off) y += t;
        }
        wt[lane] = y;
    }
    __syncthreads();
    if (wid > 0) x += wt[wid - 1];
    if (i < N_NODES) g_row_start[i] = x - v;
    if (threadIdx.x == SCAN_B - 1) g_bsum[blockIdx.x] = x;
}

// ---------------- scan3: add inter-block offsets (inline reduce of 49 block sums) ----------------
__global__ void k_scan3() {
    __shared__ int s_w[2];
    __shared__ int s_off;
    int t = threadIdx.x;
    if (t < 64) {
        int v = (t < (int)blockIdx.x) ? g_bsum[t] : 0;   // blockIdx.x <= 48 < 64
#pragma unroll
        for (int off = 16; off; off >>= 1) v += __shfl_down_sync(0xffffffffu, v, off);
        if ((t & 31) == 0) s_w[t >> 5] = v;
    }
    __syncthreads();
    if (t == 0) s_off = s_w[0] + s_w[1];
    __syncthreads();
    int i = blockIdx.x * SCAN_B + t;
    if (i < N_NODES) {
        int rs = g_row_start[i] + s_off;
        g_row_start[i] = rs;
        g_cursor[i]    = rs;
    }
}

// ---------------- fill: 4 edges per thread ----------------
__global__ __launch_bounds__(256) void k_fill(const int* __restrict__ src, const int* __restrict__ dst) {
    int base = blockIdx.x * 1024 + threadIdx.x;
    int s[4], d[4];
    bool ok[4];
#pragma unroll
    for (int k = 0; k < 4; k++) {
        int e = base + k * 256;
        ok[k] = e < N_EDGES;
        s[k] = ok[k] ? src[e] : 0;
        d[k] = ok[k] ? dst[e] : 0;
    }
    int pos[4];
#pragma unroll
    for (int k = 0; k < 4; k++)
        if (ok[k]) pos[k] = atomicAdd(&g_cursor[clampi(d[k])], 1);
#pragma unroll
    for (int k = 0; k < 4; k++)
        if (ok[k]) g_csr_src[pos[k]] = clampi(s[k]);
}

// ---------------- GEMM1 TM=128: z1 = fp16((h*norm_out)@W1) ----------------
__global__ __launch_bounds__(256) void k_gemm1(const float* __restrict__ X,
                                               const float* __restrict__ W,
                                               __half* __restrict__ Y) {
    constexpr int LDA = 136, LDB = 136;
    extern __shared__ __half sm[];
    __half* sA = sm;
    __half* sB = sm + 128 * LDA;

    int t = threadIdx.x;
    int row0 = blockIdx.x * 128;

    {
        int kq = t & 15;
        int rr = t >> 4;
        const float4* X4 = (const float4*)X;
        const float4* W4 = (const float4*)W;
#pragma unroll
        for (int p = 0; p < 8; p++) {
            int r  = rr + p * 16;
            int gr = min(row0 + r, N_NODES - 1);
            float no = g_norm_out[gr];
            float4 v0 = X4[(size_t)gr * 32 + kq * 2];
            float4 v1 = X4[(size_t)gr * 32 + kq * 2 + 1];
            *(uint4*)(sA + r * LDA + kq * 8) = f8_to_h8(v0, v1, no);
        }
#pragma unroll
        for (int p = 0; p < 8; p++) {
            int r = rr + p * 16;
            float4 v0 = W4[r * 32 + kq * 2];
            float4 v1 = W4[r * 32 + kq * 2 + 1];
            *(uint4*)(sB + r * LDB + kq * 8) = f8_to_h8(v0, v1, 1.0f);
        }
    }
    __syncthreads();

    int lane = t & 31;
    int wid  = t >> 5;
    int wm = wid >> 1;
    int wn = wid & 1;

    float acc[2][8][4];
#pragma unroll
    for (int i = 0; i < 2; i++)
#pragma unroll
        for (int j = 0; j < 8; j++)
#pragma unroll
            for (int q = 0; q < 4; q++) acc[i][j][q] = 0.f;

    uint32_t aaddr = s2u(sA) + (((wm * 32 + (lane & 15)) * LDA + (lane >> 4) * 8)) * 2;
    uint32_t baddr = s2u(sB) + ((((lane & 7) + ((lane >> 3) & 1) * 8) * LDB
                                 + wn * 64 + (lane >> 4) * 8)) * 2;

#pragma unroll
    for (int ks = 0; ks < 8; ks++) {
        uint32_t a[2][4];
        ldsm_x4(a[0][0], a[0][1], a[0][2], a[0][3], aaddr + ks * 32);
        ldsm_x4(a[1][0], a[1][1], a[1][2], a[1][3], aaddr + 16 * LDA * 2 + ks * 32);
        uint32_t b[8][2];
#pragma unroll
        for (int ntp = 0; ntp < 4; ntp++) {
            uint32_t r0, r1, r2, r3;
            ldsm_x4t(r0, r1, r2, r3, baddr + ks * 16 * LDB * 2 + ntp * 32);
            b[2 * ntp][0] = r0; b[2 * ntp][1] = r1;
            b[2 * ntp + 1][0] = r2; b[2 * ntp + 1][1] = r3;
        }
#pragma unroll
        for (int mt = 0; mt < 2; mt++)
#pragma unroll
            for (int nt = 0; nt < 8; nt++)
                mma16816(acc[mt][nt], a[mt], b[nt]);
    }

#pragma unroll
    for (int mt = 0; mt < 2; mt++) {
        int r1 = row0 + wm * 32 + mt * 16 + (lane >> 2);
#pragma unroll
        for (int nt = 0; nt < 8; nt++) {
            int c = wn * 64 + nt * 8 + ((lane & 3) << 1);
            __half2 lo = __floats2half2_rn(acc[mt][nt][0], acc[mt][nt][1]);
            __half2 hi = __floats2half2_rn(acc[mt][nt][2], acc[mt][nt][3]);
            if (r1 < N_NODES)     *(__half2*)(Y + (size_t)r1 * 128 + c)       = lo;
            if (r1 + 8 < N_NODES) *(__half2*)(Y + (size_t)(r1 + 8) * 128 + c) = hi;
        }
    }
}

// ---------------- gather1: h1 = fp16( relu( (sum z1[s]) * ni + b1 ) * no ) ----------------
// one warp per node; 4-edge batches for MLP; HADD2 per pair (same numerics as R14).
__global__ void k_gather1(const float* __restrict__ b1) {
    int warp = (blockIdx.x * blockDim.x + threadIdx.x) >> 5;
    int lane = threadIdx.x & 31;
    if (warp >= N_NODES) return;
    int start = g_row_start[warp];
    int end   = start + g_atomic[A_DEGI + warp];
    const uint2* Z2 = (const uint2*)g_z1h;
    float4 acc = make_float4(0.f, 0.f, 0.f, 0.f);
    int p = start;
    for (; p + 3 < end; p += 4) {
        int s0 = __ldg(&g_csr_src[p]);
        int s1 = __ldg(&g_csr_src[p + 1]);
        int s2 = __ldg(&g_csr_src[p + 2]);
        int s3 = __ldg(&g_csr_src[p + 3]);
        uint2 v0 = __ldg(&Z2[(size_t)s0 * 32 + lane]);
        uint2 v1 = __ldg(&Z2[(size_t)s1 * 32 + lane]);
        uint2 v2 = __ldg(&Z2[(size_t)s2 * 32 + lane]);
        uint2 v3 = __ldg(&Z2[(size_t)s3 * 32 + lane]);
        uint32_t a0 = hadd2(v0.x, v1.x);
        uint32_t a1 = hadd2(v0.y, v1.y);
        uint32_t c0 = hadd2(v2.x, v3.x);
        uint32_t c1 = hadd2(v2.y, v3.y);
        float2 fa0 = __half22float2(*(__half2*)&a0);
        float2 fa1 = __half22float2(*(__half2*)&a1);
        float2 fc0 = __half22float2(*(__half2*)&c0);
        float2 fc1 = __half22float2(*(__half2*)&c1);
        acc.x += fa0.x + fc0.x; acc.y += fa0.y + fc0.y;
        acc.z += fa1.x + fc1.x; acc.w += fa1.y + fc1.y;
    }
    for (; p + 1 < end; p += 2) {
        int s0 = __ldg(&g_csr_src[p]);
        int s1 = __ldg(&g_csr_src[p + 1]);
        uint2 v0 = __ldg(&Z2[(size_t)s0 * 32 + lane]);
        uint2 v1 = __ldg(&Z2[(size_t)s1 * 32 + lane]);
        uint32_t a0 = hadd2(v0.x, v1.x);
        uint32_t a1 = hadd2(v0.y, v1.y);
        float2 f0 = __half22float2(*(__half2*)&a0);
        float2 f1 = __half22float2(*(__half2*)&a1);
        acc.x += f0.x; acc.y += f0.y; acc.z += f1.x; acc.w += f1.y;
    }
    if (p < end) {
        int s = __ldg(&g_csr_src[p]);
        uint2 v = __ldg(&Z2[(size_t)s * 32 + lane]);
        float2 f0 = __half22float2(*(__half2*)&v.x);
        float2 f1 = __half22float2(*(__half2*)&v.y);
        acc.x += f0.x; acc.y += f0.y; acc.z += f1.x; acc.w += f1.y;
    }
    float ni = g_norm_in[warp];
    float no = g_norm_out[warp];
    float4 b = ((const float4*)b1)[lane];
    float4 o;
    o.x = fmaxf(fmaf(acc.x, ni, b.x), 0.f) * no;
    o.y = fmaxf(fmaf(acc.y, ni, b.y), 0.f) * no;
    o.z = fmaxf(fmaf(acc.z, ni, b.z), 0.f) * no;
    o.w = fmaxf(fmaf(acc.w, ni, b.w), 0.f) * no;
    __half2 h0 = __floats2half2_rn(o.x, o.y);
    __half2 h1v = __floats2half2_rn(o.z, o.w);
    uint2 u;
    u.x = *(uint32_t*)&h0; u.y = *(uint32_t*)&h1v;
    ((uint2*)g_h1h)[(size_t)warp * 32 + lane] = u;
}

// ---------------- tensor-core GEMM2: z2 = fp16( h1 @ W2 ), TM=128 ----------------
__global__ __launch_bounds__(256) void k_gemm2(const __half* __restrict__ Xh,
                                               const float* __restrict__ W,
                                               __half* __restrict__ Y) {
    constexpr int LDA = 136, LDB = 72;
    extern __shared__ __half sm[];
    __half* sA = sm;
    __half* sB = sm + 128 * LDA;

    int t = threadIdx.x;
    int row0 = blockIdx.x * 128;

    {
        int kq = t & 15;
        int rr = t >> 4;
        const uint4* X4 = (const uint4*)Xh;
#pragma unroll
        for (int p = 0; p < 8; p++) {
            int r  = rr + p * 16;
            int gr = min(row0 + r, N_NODES - 1);
            *(uint4*)(sA + r * LDA + kq * 8) = X4[(size_t)gr * 16 + kq];
        }
        int cq = t & 7;
        int r2 = t >> 3;
        const float4* W4 = (const float4*)W;
#pragma unroll
        for (int p = 0; p < 4; p++) {
            int r = r2 + p * 32;
            float4 v0 = W4[r * 16 + cq * 2];
            float4 v1 = W4[r * 16 + cq * 2 + 1];
            *(uint4*)(sB + r * LDB + cq * 8) = f8_to_h8(v0, v1, 1.0f);
        }
    }
    __syncthreads();

    int lane = t & 31;
    int wid  = t >> 5;
    int wm = wid >> 1;
    int wn = wid & 1;

    float acc[2][4][4];
#pragma unroll
    for (int i = 0; i < 2; i++)
#pragma unroll
        for (int j = 0; j < 4; j++)
#pragma unroll
            for (int q = 0; q < 4; q++) acc[i][j][q] = 0.f;

    uint32_t aaddr = s2u(sA) + (((wm * 32 + (lane & 15)) * LDA + (lane >> 4) * 8)) * 2;
    uint32_t baddr = s2u(sB) + ((((lane & 7) + ((lane >> 3) & 1) * 8) * LDB
                                 + wn * 32 + (lane >> 4) * 8)) * 2;

#pragma unroll
    for (int ks = 0; ks < 8; ks++) {
        uint32_t a[2][4];
        ldsm_x4(a[0][0], a[0][1], a[0][2], a[0][3], aaddr + ks * 32);
        ldsm_x4(a[1][0], a[1][1], a[1][2], a[1][3], aaddr + 16 * LDA * 2 + ks * 32);
        uint32_t b[4][2];
#pragma unroll
        for (int ntp = 0; ntp < 2; ntp++) {
            uint32_t r0, r1, r2, r3;
            ldsm_x4t(r0, r1, r2, r3, baddr + ks * 16 * LDB * 2 + ntp * 32);
            b[2 * ntp][0] = r0; b[2 * ntp][1] = r1;
            b[2 * ntp + 1][0] = r2; b[2 * ntp + 1][1] = r3;
        }
#pragma unroll
        for (int mt = 0; mt < 2; mt++)
#pragma unroll
            for (int nt = 0; nt < 4; nt++)
                mma16816(acc[mt][nt], a[mt], b[nt]);
    }

#pragma unroll
    for (int mt = 0; mt < 2; mt++) {
        int r1 = row0 + wm * 32 + mt * 16 + (lane >> 2);
#pragma unroll
        for (int nt = 0; nt < 4; nt++) {
            int c = wn * 32 + nt * 8 + ((lane & 3) << 1);
            __half2 lo = __floats2half2_rn(acc[mt][nt][0], acc[mt][nt][1]);
            __half2 hi = __floats2half2_rn(acc[mt][nt][2], acc[mt][nt][3]);
            if (r1 < N_NODES)     *(__half2*)(Y + (size_t)r1 * 64 + c)       = lo;
            if (r1 + 8 < N_NODES) *(__half2*)(Y + (size_t)(r1 + 8) * 64 + c) = hi;
        }
    }
}

// ---------------- gather2: out = relu( (sum z2[src]) * norm_in + b2 ) ----------------
// one warp per node; 4-edge batches; HADD2 per pair.
__global__ void k_gather2(const float* __restrict__ b2, float* __restrict__ out) {
    int warp = (blockIdx.x * blockDim.x + threadIdx.x) >> 5;
    int lane = threadIdx.x & 31;
    if (warp >= N_NODES) return;
    int start = g_row_start[warp];
    int end   = start + g_atomic[A_DEGI + warp];
    const uint32_t* Y1 = (const uint32_t*)g_z2h;
    float2 acc = make_float2(0.f, 0.f);
    int p = start;
    for (; p + 3 < end; p += 4) {
        int s0 = __ldg(&g_csr_src[p]);
        int s1 = __ldg(&g_csr_src[p + 1]);
        int s2 = __ldg(&g_csr_src[p + 2]);
        int s3 = __ldg(&g_csr_src[p + 3]);
        uint32_t v0 = __ldg(&Y1[(size_t)s0 * 32 + lane]);
        uint32_t v1 = __ldg(&Y1[(size_t)s1 * 32 + lane]);
        uint32_t v2 = __ldg(&Y1[(size_t)s2 * 32 + lane]);
        uint32_t v3 = __ldg(&Y1[(size_t)s3 * 32 + lane]);
        uint32_t a0 = hadd2(v0, v1);
        uint32_t a1 = hadd2(v2, v3);
        float2 f0 = __half22float2(*(__half2*)&a0);
        float2 f1 = __half22float2(*(__half2*)&a1);
        acc.x += f0.x + f1.x; acc.y += f0.y + f1.y;
    }
    for (; p + 1 < end; p += 2) {
        int s0 = __ldg(&g_csr_src[p]);
        int s1 = __ldg(&g_csr_src[p + 1]);
        uint32_t v0 = __ldg(&Y1[(size_t)s0 * 32 + lane]);
        uint32_t v1 = __ldg(&Y1[(size_t)s1 * 32 + lane]);
        uint32_t a0 = hadd2(v0, v1);
        float2 f = __half22float2(*(__half2*)&a0);
        acc.x += f.x; acc.y += f.y;
    }
    if (p < end) {
        int s = __ldg(&g_csr_src[p]);
        uint32_t v = __ldg(&Y1[(size_t)s * 32 + lane]);
        float2 f = __half22float2(*(__half2*)&v);
        acc.x += f.x; acc.y += f.y;
    }
    float ni = g_norm_in[warp];
    float2 b = ((const float2*)b2)[lane];
    float2 o;
    o.x = fmaxf(fmaf(acc.x, ni, b.x), 0.f);
    o.y = fmaxf(fmaf(acc.y, ni, b.y), 0.f);
    ((float2*)out)[(size_t)warp * 32 + lane] = o;
}

// ---------------- launch: DAG via stream-capture fork/join ----------------
struct SideRes {
    cudaStream_t s;
    cudaEvent_t  e0, e1;
    SideRes() {
        cudaStreamCreateWithFlags(&s, cudaStreamNonBlocking);
        cudaEventCreateWithFlags(&e0, cudaEventDisableTiming);
        cudaEventCreateWithFlags(&e1, cudaEventDisableTiming);
    }
};

extern "C" void kernel_launch(void* const* d_in, const int* in_sizes, int n_in,
                              void* d_out, int out_size) {
    const float* h   = (const float*)d_in[0];
    const float* W1  = (const float*)d_in[1];
    const float* b1  = (const float*)d_in[2];
    const float* W2  = (const float*)d_in[3];
    const float* b2  = (const float*)d_in[4];
    const int*   src = (const int*)d_in[5];   // JAX x64-disabled: int32
    const int*   dst = (const int*)d_in[6];
    float*       out = (float*)d_out;

    static SideRes R;   // streams/events created once (resource init, work identical per call)

    __half *z1h, *h1h, *z2h;
    int* atom;
    cudaGetSymbolAddress((void**)&z1h,  g_z1h);
    cudaGetSymbolAddress((void**)&h1h,  g_h1h);
    cudaGetSymbolAddress((void**)&z2h,  g_z2h);
    cudaGetSymbolAddress((void**)&atom, g_atomic);

    const int SMEM1 = (128 * 136 + 128 * 136) * 2;   // 69632 B
    const int SMEM2 = (128 * 136 + 128 * 72) * 2;    // 53248 B
    cudaFuncSetAttribute((const void*)k_gemm1,
                         cudaFuncAttributeMaxDynamicSharedMemorySize, SMEM1);
    cudaFuncSetAttribute((const void*)k_gemm2,
                         cudaFuncAttributeMaxDynamicSharedMemorySize, SMEM2);

    const int T = 256;

    // main stream: degrees -> norms
    cudaMemsetAsync(atom, 0, A_TOTAL * sizeof(int));
    k_deg <<<DEGB, T>>>(src, dst);
    k_norm<<<(N_NODES + T - 1) / T, T>>>();

    // fork: side stream runs GEMM1 (needs only h, W1, norm_out)
    cudaEventRecord(R.e0, 0);
    cudaStreamWaitEvent(R.s, R.e0, 0);
    k_gemm1<<<GB1, T, SMEM1, R.s>>>(h, W1, z1h);
    cudaEventRecord(R.e1, R.s);

    // main stream continues: scan -> CSR fill (concurrent with GEMM1)
    k_scan1<<<SCAN_NB, SCAN_B>>>();
    k_scan3<<<SCAN_NB, SCAN_B>>>();
    k_fill <<<FILLB, T>>>(src, dst);

    // join: gather1 needs both CSR and z1
    cudaStreamWaitEvent(0, R.e1, 0);
    k_gather1<<<(N_NODES * 32 + T - 1) / T, T>>>(b1);
    k_gemm2 <<<GB1, T, SMEM2>>>(h1h, W2, z2h);
    k_gather2<<<(N_NODES * 32 + T - 1) / T, T>>>(b2, out);
}

// round 16
// speedup vs baseline: 1.0792x; 1.0792x over previous
#include <cuda_runtime.h>
#include <cuda_fp16.h>
#include <cstdint>

#define N_NODES 50000
#define N_EDGES 800000
#define F_IN    128
#define F_HID   128
#define F_OUT   64
#define SCAN_B  1024
#define SCAN_NB ((N_NODES + SCAN_B - 1) / SCAN_B)   // 49
#define GB1     ((N_NODES + 127) / 128)             // 391 gemm blocks (TM=128)
#define DEGB    ((N_EDGES + 255) / 256)             // 3125 deg blocks
#define WCONVB  12                                  // W fp16-conversion blocks (3072 chunks of 8)
#define FILLB   ((N_EDGES + 1023) / 1024)           // 782 fill blocks (4 edges/thread)

// ---- zero-init region (single memset): [0,N)=deg_out [N,2N)=deg_in ----
#define A_DEGO  0
#define A_DEGI  N_NODES
#define A_TOTAL (2 * N_NODES)
__device__ __align__(16) int    g_atomic[A_TOTAL];

__device__ __align__(16) __half g_w1h[F_IN * F_HID];     // W1 as fp16 [128,128]
__device__ __align__(16) __half g_w2h[F_HID * F_OUT];    // W2 as fp16 [128,64]
__device__ __align__(16) __half g_z1h[N_NODES * F_HID];  // (h*norm_out)@W1      fp16 [N,128]
__device__ __align__(16) __half g_h1h[N_NODES * F_HID];  // relu layer1*norm_out fp16 [N,128]
__device__ __align__(16) __half g_z2h[N_NODES * F_OUT];  // h1@W2                fp16 [N,64]
__device__ __align__(16) float  g_norm_out[N_NODES];
__device__ __align__(16) float  g_norm_in [N_NODES];
__device__ __align__(16) int    g_row_start[N_NODES];
__device__ __align__(16) int    g_cursor[N_NODES];
__device__ __align__(16) int    g_bsum[64];
__device__ __align__(16) int    g_csr_src[N_EDGES];

__device__ __forceinline__ int clampi(int v) {
    return v < 0 ? 0 : (v >= N_NODES ? N_NODES - 1 : v);
}

__device__ __forceinline__ uint32_t s2u(const void* p) {
    uint32_t a;
    asm("{ .reg .u64 t; cvta.to.shared.u64 t, %1; cvt.u32.u64 %0, t; }" : "=r"(a) : "l"(p));
    return a;
}

__device__ __forceinline__ void ldsm_x4(uint32_t& r0, uint32_t& r1, uint32_t& r2, uint32_t& r3, uint32_t addr) {
    asm volatile("ldmatrix.sync.aligned.m8n8.x4.shared.b16 {%0,%1,%2,%3}, [%4];"
                 : "=r"(r0), "=r"(r1), "=r"(r2), "=r"(r3) : "r"(addr));
}

__device__ __forceinline__ void ldsm_x4t(uint32_t& r0, uint32_t& r1, uint32_t& r2, uint32_t& r3, uint32_t addr) {
    asm volatile("ldmatrix.sync.aligned.m8n8.x4.trans.shared.b16 {%0,%1,%2,%3}, [%4];"
                 : "=r"(r0), "=r"(r1), "=r"(r2), "=r"(r3) : "r"(addr));
}

__device__ __forceinline__ void mma16816(float* c, const uint32_t* a, const uint32_t* b) {
    asm volatile("mma.sync.aligned.m16n8k16.row.col.f32.f16.f16.f32 "
                 "{%0,%1,%2,%3}, {%4,%5,%6,%7}, {%8,%9}, {%0,%1,%2,%3};"
                 : "+f"(c[0]), "+f"(c[1]), "+f"(c[2]), "+f"(c[3])
                 : "r"(a[0]), "r"(a[1]), "r"(a[2]), "r"(a[3]), "r"(b[0]), "r"(b[1]));
}

__device__ __forceinline__ uint32_t hadd2(uint32_t a, uint32_t b) {
    uint32_t c;
    asm("add.f16x2 %0, %1, %2;" : "=r"(c) : "r"(a), "r"(b));
    return c;
}

__device__ __forceinline__ uint4 f8_to_h8(float4 v0, float4 v1, float s) {
    __half2 h0 = __floats2half2_rn(v0.x * s, v0.y * s);
    __half2 h1 = __floats2half2_rn(v0.z * s, v0.w * s);
    __half2 h2 = __floats2half2_rn(v1.x * s, v1.y * s);
    __half2 h3 = __floats2half2_rn(v1.z * s, v1.w * s);
    uint4 u;
    u.x = *(uint32_t*)&h0; u.y = *(uint32_t*)&h1;
    u.z = *(uint32_t*)&h2; u.w = *(uint32_t*)&h3;
    return u;
}

// ======= deg + W fp16 conversion (grid-fused; W-conv blocks are ~free) =======
__global__ void k_degW(const int* __restrict__ src, const int* __restrict__ dst,
                       const float* __restrict__ W1, const float* __restrict__ W2) {
    if (blockIdx.x < DEGB) {
        int e = blockIdx.x * 256 + threadIdx.x;
        if (e < N_EDGES) {
            atomicAdd(&g_atomic[A_DEGO + clampi(src[e])], 1);
            atomicAdd(&g_atomic[A_DEGI + clampi(dst[e])], 1);
        }
        return;
    }
    // W conversion: chunk = 8 floats -> 8 halves. W1: 2048 chunks, W2: 1024 chunks.
    int idx = (blockIdx.x - DEGB) * 256 + threadIdx.x;
    if (idx < 2048) {
        const float4* W4 = (const float4*)W1;
        ((uint4*)g_w1h)[idx] = f8_to_h8(W4[idx * 2], W4[idx * 2 + 1], 1.0f);
    } else if (idx < 3072) {
        int j = idx - 2048;
        const float4* W4 = (const float4*)W2;
        ((uint4*)g_w2h)[j] = f8_to_h8(W4[j * 2], W4[j * 2 + 1], 1.0f);
    }
}

// ---------------- scan1: block-local scan of deg_in + fused norms ----------------
__global__ void k_scan1() {
    __shared__ int wt[32];
    int i    = blockIdx.x * SCAN_B + threadIdx.x;
    int lane = threadIdx.x & 31;
    int wid  = threadIdx.x >> 5;
    int v = (i < N_NODES) ? g_atomic[A_DEGI + i] : 0;
    if (i < N_NODES) {
        g_norm_in [i] = rsqrtf((float)max(v, 1));
        g_norm_out[i] = rsqrtf((float)max(g_atomic[A_DEGO + i], 1));
    }
    int x = v;
#pragma unroll
    for (int off = 1; off < 32; off <<= 1) {
        int t = __shfl_up_sync(0xffffffffu, x, off);
        if (lane >= off) x += t;
    }
    if (lane == 31) wt[wid] = x;
    __syncthreads();
    if (wid == 0) {
        int y = wt[lane];
#pragma unroll
        for (int off = 1; off < 32; off <<= 1) {
            int t = __shfl_up_sync(0xffffffffu, y, off);
            if (lane >= off) y += t;
        }
        wt[lane] = y;
    }
    __syncthreads();
    if (wid > 0) x += wt[wid - 1];
    if (i < N_NODES) g_row_start[i] = x - v;
    if (threadIdx.x == SCAN_B - 1) g_bsum[blockIdx.x] = x;
}

// ---------------- scan3: add inter-block offsets (inline reduce of 49 block sums) ----------------
__global__ void k_scan3() {
    __shared__ int s_w[2];
    __shared__ int s_off;
    int t = threadIdx.x;
    if (t < 64) {
        int v = (t < (int)blockIdx.x) ? g_bsum[t] : 0;   // blockIdx.x <= 48 < 64
#pragma unroll
        for (int off = 16; off; off >>= 1) v += __shfl_down_sync(0xffffffffu, v, off);
        if ((t & 31) == 0) s_w[t >> 5] = v;
    }
    __syncthreads();
    if (t == 0) s_off = s_w[0] + s_w[1];
    __syncthreads();
    int i = blockIdx.x * SCAN_B + t;
    if (i < N_NODES) {
        int rs = g_row_start[i] + s_off;
        g_row_start[i] = rs;
        g_cursor[i]    = rs;
    }
}

// ======= fused C: blocks [0,GB1) = GEMM1 TM=128 (z1 = fp16((h*norm_out)@W1));
//                  blocks [GB1,GB1+FILLB) = CSR fill (4 edges/thread). =======
__global__ __launch_bounds__(256) void k_fusedC(const float* __restrict__ X,
                                                __half* __restrict__ Y,
                                                const int* __restrict__ src,
                                                const int* __restrict__ dst) {
    if (blockIdx.x >= GB1) {
        // ---- fill part ----
        int base = (blockIdx.x - GB1) * 1024 + threadIdx.x;
        int s[4], d[4];
        bool ok[4];
#pragma unroll
        for (int k = 0; k < 4; k++) {
            int e = base + k * 256;
            ok[k] = e < N_EDGES;
            s[k] = ok[k] ? src[e] : 0;
            d[k] = ok[k] ? dst[e] : 0;
        }
        int pos[4];
#pragma unroll
        for (int k = 0; k < 4; k++)
            if (ok[k]) pos[k] = atomicAdd(&g_cursor[clampi(d[k])], 1);
#pragma unroll
        for (int k = 0; k < 4; k++)
            if (ok[k]) g_csr_src[pos[k]] = clampi(s[k]);
        return;
    }

    // ---- GEMM1 part: 128x128x128, 8 warps (4M x 2N), warp tile 32x64 ----
    constexpr int LDA = 136, LDB = 136;
    extern __shared__ __half sm[];
    __half* sA = sm;
    __half* sB = sm + 128 * LDA;

    int t = threadIdx.x;
    int row0 = blockIdx.x * 128;

    {
        int kq = t & 15;
        int rr = t >> 4;
        const float4* X4 = (const float4*)X;
#pragma unroll
        for (int p = 0; p < 8; p++) {
            int r  = rr + p * 16;
            int gr = min(row0 + r, N_NODES - 1);
            float no = g_norm_out[gr];
            float4 v0 = X4[(size_t)gr * 32 + kq * 2];
            float4 v1 = X4[(size_t)gr * 32 + kq * 2 + 1];
            *(uint4*)(sA + r * LDA + kq * 8) = f8_to_h8(v0, v1, no);
        }
#pragma unroll
        for (int p = 0; p < 8; p++) {           // W1 already fp16: pure copy
            int r = rr + p * 16;
            *(uint4*)(sB + r * LDB + kq * 8) =
                *(const uint4*)(g_w1h + r * F_HID + kq * 8);
        }
    }
    __syncthreads();

    int lane = t & 31;
    int wid  = t >> 5;
    int wm = wid >> 1;
    int wn = wid & 1;

    float acc[2][8][4];
#pragma unroll
    for (int i = 0; i < 2; i++)
#pragma unroll
        for (int j = 0; j < 8; j++)
#pragma unroll
            for (int q = 0; q < 4; q++) acc[i][j][q] = 0.f;

    uint32_t aaddr = s2u(sA) + (((wm * 32 + (lane & 15)) * LDA + (lane >> 4) * 8)) * 2;
    uint32_t baddr = s2u(sB) + ((((lane & 7) + ((lane >> 3) & 1) * 8) * LDB
                                 + wn * 64 + (lane >> 4) * 8)) * 2;

#pragma unroll
    for (int ks = 0; ks < 8; ks++) {
        uint32_t a[2][4];
        ldsm_x4(a[0][0], a[0][1], a[0][2], a[0][3], aaddr + ks * 32);
        ldsm_x4(a[1][0], a[1][1], a[1][2], a[1][3], aaddr + 16 * LDA * 2 + ks * 32);
        uint32_t b[8][2];
#pragma unroll
        for (int ntp = 0; ntp < 4; ntp++) {
            uint32_t r0, r1, r2, r3;
            ldsm_x4t(r0, r1, r2, r3, baddr + ks * 16 * LDB * 2 + ntp * 32);
            b[2 * ntp][0] = r0; b[2 * ntp][1] = r1;
            b[2 * ntp + 1][0] = r2; b[2 * ntp + 1][1] = r3;
        }
#pragma unroll
        for (int mt = 0; mt < 2; mt++)
#pragma unroll
            for (int nt = 0; nt < 8; nt++)
                mma16816(acc[mt][nt], a[mt], b[nt]);
    }

#pragma unroll
    for (int mt = 0; mt < 2; mt++) {
        int r1 = row0 + wm * 32 + mt * 16 + (lane >> 2);
#pragma unroll
        for (int nt = 0; nt < 8; nt++) {
            int c = wn * 64 + nt * 8 + ((lane & 3) << 1);
            __half2 lo = __floats2half2_rn(acc[mt][nt][0], acc[mt][nt][1]);
            __half2 hi = __floats2half2_rn(acc[mt][nt][2], acc[mt][nt][3]);
            if (r1 < N_NODES)     *(__half2*)(Y + (size_t)r1 * 128 + c)       = lo;
            if (r1 + 8 < N_NODES) *(__half2*)(Y + (size_t)(r1 + 8) * 128 + c) = hi;
        }
    }
}

// ---------------- gather1: h1 = fp16( relu( (sum z1[s]) * ni + b1 ) * no ) ----------------
// one warp per node; 4-edge batches for MLP; HADD2 per pair.
__global__ void k_gather1(const float* __restrict__ b1) {
    int warp = (blockIdx.x * blockDim.x + threadIdx.x) >> 5;
    int lane = threadIdx.x & 31;
    if (warp >= N_NODES) return;
    int start = g_row_start[warp];
    int end   = start + g_atomic[A_DEGI + warp];
    const uint2* Z2 = (const uint2*)g_z1h;
    float4 acc = make_float4(0.f, 0.f, 0.f, 0.f);
    int p = start;
    for (; p + 3 < end; p += 4) {
        int s0 = __ldg(&g_csr_src[p]);
        int s1 = __ldg(&g_csr_src[p + 1]);
        int s2 = __ldg(&g_csr_src[p + 2]);
        int s3 = __ldg(&g_csr_src[p + 3]);
        uint2 v0 = __ldg(&Z2[(size_t)s0 * 32 + lane]);
        uint2 v1 = __ldg(&Z2[(size_t)s1 * 32 + lane]);
        uint2 v2 = __ldg(&Z2[(size_t)s2 * 32 + lane]);
        uint2 v3 = __ldg(&Z2[(size_t)s3 * 32 + lane]);
        uint32_t a0 = hadd2(v0.x, v1.x);
        uint32_t a1 = hadd2(v0.y, v1.y);
        uint32_t c0 = hadd2(v2.x, v3.x);
        uint32_t c1 = hadd2(v2.y, v3.y);
        float2 fa0 = __half22float2(*(__half2*)&a0);
        float2 fa1 = __half22float2(*(__half2*)&a1);
        float2 fc0 = __half22float2(*(__half2*)&c0);
        float2 fc1 = __half22float2(*(__half2*)&c1);
        acc.x += fa0.x + fc0.x; acc.y += fa0.y + fc0.y;
        acc.z += fa1.x + fc1.x; acc.w += fa1.y + fc1.y;
    }
    for (; p + 1 < end; p += 2) {
        int s0 = __ldg(&g_csr_src[p]);
        int s1 = __ldg(&g_csr_src[p + 1]);
        uint2 v0 = __ldg(&Z2[(size_t)s0 * 32 + lane]);
        uint2 v1 = __ldg(&Z2[(size_t)s1 * 32 + lane]);
        uint32_t a0 = hadd2(v0.x, v1.x);
        uint32_t a1 = hadd2(v0.y, v1.y);
        float2 f0 = __half22float2(*(__half2*)&a0);
        float2 f1 = __half22float2(*(__half2*)&a1);
        acc.x += f0.x; acc.y += f0.y; acc.z += f1.x; acc.w += f1.y;
    }
    if (p < end) {
        int s = __ldg(&g_csr_src[p]);
        uint2 v = __ldg(&Z2[(size_t)s * 32 + lane]);
        float2 f0 = __half22float2(*(__half2*)&v.x);
        float2 f1 = __half22float2(*(__half2*)&v.y);
        acc.x += f0.x; acc.y += f0.y; acc.z += f1.x; acc.w += f1.y;
    }
    float ni = g_norm_in[warp];
    float no = g_norm_out[warp];
    float4 b = ((const float4*)b1)[lane];
    float4 o;
    o.x = fmaxf(fmaf(acc.x, ni, b.x), 0.f) * no;
    o.y = fmaxf(fmaf(acc.y, ni, b.y), 0.f) * no;
    o.z = fmaxf(fmaf(acc.z, ni, b.z), 0.f) * no;
    o.w = fmaxf(fmaf(acc.w, ni, b.w), 0.f) * no;
    __half2 h0 = __floats2half2_rn(o.x, o.y);
    __half2 h1v = __floats2half2_rn(o.z, o.w);
    uint2 u;
    u.x = *(uint32_t*)&h0; u.y = *(uint32_t*)&h1v;
    ((uint2*)g_h1h)[(size_t)warp * 32 + lane] = u;
}

// ---------------- tensor-core GEMM2: z2 = fp16( h1 @ W2 ), TM=128 ----------------
__global__ __launch_bounds__(256) void k_gemm2(__half* __restrict__ Y) {
    constexpr int LDA = 136, LDB = 72;
    extern __shared__ __half sm[];
    __half* sA = sm;
    __half* sB = sm + 128 * LDA;

    int t = threadIdx.x;
    int row0 = blockIdx.x * 128;

    {
        int kq = t & 15;
        int rr = t >> 4;
        const uint4* X4 = (const uint4*)g_h1h;
#pragma unroll
        for (int p = 0; p < 8; p++) {
            int r  = rr + p * 16;
            int gr = min(row0 + r, N_NODES - 1);
            *(uint4*)(sA + r * LDA + kq * 8) = X4[(size_t)gr * 16 + kq];
        }
        int cq = t & 7;
        int r2 = t >> 3;
#pragma unroll
        for (int p = 0; p < 4; p++) {           // W2 already fp16: pure copy
            int r = r2 + p * 32;
            *(uint4*)(sB + r * LDB + cq * 8) =
                *(const uint4*)(g_w2h + r * F_OUT + cq * 8);
        }
    }
    __syncthreads();

    int lane = t & 31;
    int wid  = t >> 5;
    int wm = wid >> 1;
    int wn = wid & 1;

    float acc[2][4][4];
#pragma unroll
    for (int i = 0; i < 2; i++)
#pragma unroll
        for (int j = 0; j < 4; j++)
#pragma unroll
            for (int q = 0; q < 4; q++) acc[i][j][q] = 0.f;

    uint32_t aaddr = s2u(sA) + (((wm * 32 + (lane & 15)) * LDA + (lane >> 4) * 8)) * 2;
    uint32_t baddr = s2u(sB) + ((((lane & 7) + ((lane >> 3) & 1) * 8) * LDB
                                 + wn * 32 + (lane >> 4) * 8)) * 2;

#pragma unroll
    for (int ks = 0; ks < 8; ks++) {
        uint32_t a[2][4];
        ldsm_x4(a[0][0], a[0][1], a[0][2], a[0][3], aaddr + ks * 32);
        ldsm_x4(a[1][0], a[1][1], a[1][2], a[1][3], aaddr + 16 * LDA * 2 + ks * 32);
        uint32_t b[4][2];
#pragma unroll
        for (int ntp = 0; ntp < 2; ntp++) {
            uint32_t r0, r1, r2, r3;
            ldsm_x4t(r0, r1, r2, r3, baddr + ks * 16 * LDB * 2 + ntp * 32);
            b[2 * ntp][0] = r0; b[2 * ntp][1] = r1;
            b[2 * ntp + 1][0] = r2; b[2 * ntp + 1][1] = r3;
        }
#pragma unroll
        for (int mt = 0; mt < 2; mt++)
#pragma unroll
            for (int nt = 0; nt < 4; nt++)
                mma16816(acc[mt][nt], a[mt], b[nt]);
    }

#pragma unroll
    for (int mt = 0; mt < 2; mt++) {
        int r1 = row0 + wm * 32 + mt * 16 + (lane >> 2);
#pragma unroll
        for (int nt = 0; nt < 4; nt++) {
            int c = wn * 32 + nt * 8 + ((lane & 3) << 1);
            __half2 lo = __floats2half2_rn(acc[mt][nt][0], acc[mt][nt][1]);
            __half2 hi = __floats2half2_rn(acc[mt][nt][2], acc[mt][nt][3]);
            if (r1 < N_NODES)     *(__half2*)(Y + (size_t)r1 * 64 + c)       = lo;
            if (r1 + 8 < N_NODES) *(__half2*)(Y + (size_t)(r1 + 8) * 64 + c) = hi;
        }
    }
}

// ---------------- gather2: out = relu( (sum z2[src]) * norm_in + b2 ) ----------------
// one warp per node; 4-edge batches; HADD2 per pair.
__global__ void k_gather2(const float* __restrict__ b2, float* __restrict__ out) {
    int warp = (blockIdx.x * blockDim.x + threadIdx.x) >> 5;
    int lane = threadIdx.x & 31;
    if (warp >= N_NODES) return;
    int start = g_row_start[warp];
    int end   = start + g_atomic[A_DEGI + warp];
    const uint32_t* Y1 = (const uint32_t*)g_z2h;
    float2 acc = make_float2(0.f, 0.f);
    int p = start;
    for (; p + 3 < end; p += 4) {
        int s0 = __ldg(&g_csr_src[p]);
        int s1 = __ldg(&g_csr_src[p + 1]);
        int s2 = __ldg(&g_csr_src[p + 2]);
        int s3 = __ldg(&g_csr_src[p + 3]);
        uint32_t v0 = __ldg(&Y1[(size_t)s0 * 32 + lane]);
        uint32_t v1 = __ldg(&Y1[(size_t)s1 * 32 + lane]);
        uint32_t v2 = __ldg(&Y1[(size_t)s2 * 32 + lane]);
        uint32_t v3 = __ldg(&Y1[(size_t)s3 * 32 + lane]);
        uint32_t a0 = hadd2(v0, v1);
        uint32_t a1 = hadd2(v2, v3);
        float2 f0 = __half22float2(*(__half2*)&a0);
        float2 f1 = __half22float2(*(__half2*)&a1);
        acc.x += f0.x + f1.x; acc.y += f0.y + f1.y;
    }
    for (; p + 1 < end; p += 2) {
        int s0 = __ldg(&g_csr_src[p]);
        int s1 = __ldg(&g_csr_src[p + 1]);
        uint32_t v0 = __ldg(&Y1[(size_t)s0 * 32 + lane]);
        uint32_t v1 = __ldg(&Y1[(size_t)s1 * 32 + lane]);
        uint32_t a0 = hadd2(v0, v1);
        float2 f = __half22float2(*(__half2*)&a0);
        acc.x += f.x; acc.y += f.y;
    }
    if (p < end) {
        int s = __ldg(&g_csr_src[p]);
        uint32_t v = __ldg(&Y1[(size_t)s * 32 + lane]);
        float2 f = __half22float2(*(__half2*)&v);
        acc.x += f.x; acc.y += f.y;
    }
    float ni = g_norm_in[warp];
    float2 b = ((const float2*)b2)[lane];
    float2 o;
    o.x = fmaxf(fmaf(acc.x, ni, b.x), 0.f);
    o.y = fmaxf(fmaf(acc.y, ni, b.y), 0.f);
    ((float2*)out)[(size_t)warp * 32 + lane] = o;
}

// ---------------- launch ----------------
extern "C" void kernel_launch(void* const* d_in, const int* in_sizes, int n_in,
                              void* d_out, int out_size) {
    const float* h   = (const float*)d_in[0];
    const float* W1  = (const float*)d_in[1];
    const float* b1  = (const float*)d_in[2];
    const float* W2  = (const float*)d_in[3];
    const float* b2  = (const float*)d_in[4];
    const int*   src = (const int*)d_in[5];   // JAX x64-disabled: int32
    const int*   dst = (const int*)d_in[6];
    float*       out = (float*)d_out;

    __half *z1h, *z2h;
    int* atom;
    cudaGetSymbolAddress((void**)&z1h,  g_z1h);
    cudaGetSymbolAddress((void**)&z2h,  g_z2h);
    cudaGetSymbolAddress((void**)&atom, g_atomic);

    const int SMEM1 = (128 * 136 + 128 * 136) * 2;   // 69632 B
    const int SMEM2 = (128 * 136 + 128 * 72) * 2;    // 53248 B
    cudaFuncSetAttribute((const void*)k_fusedC,
                         cudaFuncAttributeMaxDynamicSharedMemorySize, SMEM1);
    cudaFuncSetAttribute((const void*)k_gemm2,
                         cudaFuncAttributeMaxDynamicSharedMemorySize, SMEM2);

    const int T = 256;

    cudaMemsetAsync(atom, 0, A_TOTAL * sizeof(int));
    k_degW  <<<DEGB + WCONVB, T>>>(src, dst, W1, W2);         // degrees || W fp16 conversion
    k_scan1 <<<SCAN_NB, SCAN_B>>>();                          // norms + block scans
    k_scan3 <<<SCAN_NB, SCAN_B>>>();                          // offsets + cursors
    k_fusedC<<<GB1 + FILLB, T, SMEM1>>>(h, z1h, src, dst);    // gemm1 (TM=128) || CSR fill
    k_gather1<<<(N_NODES * 32 + T - 1) / T, T>>>(b1);
    k_gemm2 <<<GB1, T, SMEM2>>>(z2h);
    k_gather2<<<(N_NODES * 32 + T - 1) / T, T>>>(b2, out);
}